// round 7
// baseline (speedup 1.0000x reference)
#include <cuda_runtime.h>
#include <cstdint>
#include <math.h>

// CausalGRNEMA exact chunked scan.
//  pass1: per-(b,chunk) warp scans LC steps from 0 -> aggregate S (f-units)
//  pass2: serial combine across chunks -> exact carry-in per chunk (+ g_tab)
//  pass3: per-(b,chunk) warp rescans with carry-in; cp.async 4-stage smem ring
//         decouples DRAM latency from the compute/reduce chain; LC=32 -> 512
//         blocks for ~3 blocks/SM. Channel mean is warp-internal (16 ch/lane).
// State scaled: f = ema/OMA, f' = alpha*f + x^2.

#define ALPHA   0.99f
#define OMA     0.01f
#define EPSF    1e-6f
#define EMAINIT 1e-4f

static constexpr int B  = 16;
static constexpr int T  = 8192;
static constexpr int C  = 512;
static constexpr int C4 = C / 4;          // 128 float4 columns
static constexpr int LC = 32;             // timesteps per warp task
static constexpr int NCH = T / LC;        // 256 chunks
static constexpr int WPB = 8;             // warps per block
static constexpr int NTASK = B * NCH;     // 4096 warp tasks
static constexpr int STAGES = 4;          // cp.async ring depth (3 in flight)

// dynamic smem: sg(128 f4) + sb(128 f4) + 8 warps * 4 stages * 128 f4
static constexpr int SMEM_F4   = 256 + WPB * STAGES * 128;
static constexpr int SMEM_BYTES = SMEM_F4 * 16;   // 69632

__device__ float2 g_tab[T];               // (EPS*D_t, EPS*sqrt(D_t))
__device__ float  g_S[NTASK * C];         // chunk aggregates (f-units)
__device__ float  g_Ein[NTASK * C];       // exact carry-in per chunk (f-units)

#define CP16(dst_u32, src_ptr) \
    asm volatile("cp.async.cg.shared.global [%0], [%1], 16;" \
                 :: "r"(dst_u32), "l"(src_ptr))
#define CP_COMMIT() asm volatile("cp.async.commit_group;")
#define CP_WAIT3()  asm volatile("cp.async.wait_group 3;")

// ---- pass1: warp-autonomous local scan, aggregate only ----
__global__ __launch_bounds__(256, 3)
void pass1_kernel(const float* __restrict__ x) {
    const int warp = threadIdx.x >> 5;
    const int lane = threadIdx.x & 31;
    const int task = blockIdx.x * WPB + warp;
    const int b = task >> 8;              // / NCH (=256)
    const int k = task & (NCH - 1);

    const float4* __restrict__ xb =
        (const float4*)x + ((size_t)b * T + (size_t)k * LC) * C4 + lane;

    float4 f[4], cur[4], nxt[4];
    #pragma unroll
    for (int j = 0; j < 4; j++) f[j] = make_float4(0.f, 0.f, 0.f, 0.f);
    #pragma unroll
    for (int j = 0; j < 4; j++) cur[j] = xb[j * 32];

    for (int t = 0; t < LC; t++) {
        if (t + 1 < LC) {
            #pragma unroll
            for (int j = 0; j < 4; j++) nxt[j] = xb[(size_t)(t + 1) * C4 + j * 32];
        }
        #pragma unroll
        for (int j = 0; j < 4; j++) {
            f[j].x = fmaf(ALPHA, f[j].x, cur[j].x * cur[j].x);
            f[j].y = fmaf(ALPHA, f[j].y, cur[j].y * cur[j].y);
            f[j].z = fmaf(ALPHA, f[j].z, cur[j].z * cur[j].z);
            f[j].w = fmaf(ALPHA, f[j].w, cur[j].w * cur[j].w);
        }
        #pragma unroll
        for (int j = 0; j < 4; j++) cur[j] = nxt[j];
    }
    float4* __restrict__ S4 = (float4*)g_S + (size_t)task * C4 + lane;
    #pragma unroll
    for (int j = 0; j < 4; j++) S4[j * 32] = f[j];
}

// ---- pass2: build g_tab + exact carry combine across chunks ----
__global__ void pass2_kernel() {
    const int idx = blockIdx.x * blockDim.x + threadIdx.x;  // 0..B*C-1 (== T)
    if (idx < T) {
        double D = 1.0 - exp((double)(idx + 1) * log(0.99)) + 1e-6;
        g_tab[idx] = make_float2((float)(1e-6 * D), (float)(1e-6 * sqrt(D)));
    }
    if (idx >= B * C) return;
    const int b = idx / C;
    const int c = idx % C;
    const float aL = (float)exp((double)LC * log(0.99));
    float E = EMAINIT / OMA;              // f-units
    #pragma unroll 8
    for (int k = 0; k < NCH; k++) {
        const size_t o = ((size_t)b * NCH + k) * C + c;
        g_Ein[o] = E;
        E = fmaf(aL, E, g_S[o]);
    }
}

// ---- pass3: cp.async-staged rescan + warp-internal channel mean + epilogue ----
__global__ __launch_bounds__(256, 3)
void pass3_kernel(const float* __restrict__ x,
                  const float* __restrict__ gamma,
                  const float* __restrict__ beta,
                  float* __restrict__ y) {
    extern __shared__ float4 sm4[];
    float4* sg = sm4;          // [0,128)
    float4* sb = sm4 + 128;    // [128,256)
    {
        const int tid = threadIdx.x;
        if (tid < 128)       sg[tid]       = ((const float4*)gamma)[tid];
        else                 sb[tid - 128] = ((const float4*)beta)[tid - 128];
    }

    const int warp = threadIdx.x >> 5;
    const int lane = threadIdx.x & 31;
    const int task = blockIdx.x * WPB + warp;
    const int b = task >> 8;
    const int k = task & (NCH - 1);
    const int tbase = k * LC;

    const float4* __restrict__ xb =
        (const float4*)x + ((size_t)b * T + tbase) * C4 + lane;
    float4* __restrict__ yb =
        (float4*)y + ((size_t)b * T + tbase) * C4 + lane;

    // per-warp smem ring
    float4* ring = sm4 + 256 + warp * (STAGES * 128);           // typed (LDS)
    const unsigned int ring_u32 =
        (unsigned int)__cvta_generic_to_shared(ring) + lane * 16;   // cp.async dst

    // prime 3 stages
    #pragma unroll
    for (int p = 0; p < STAGES - 1; p++) {
        #pragma unroll
        for (int j = 0; j < 4; j++)
            CP16(ring_u32 + p * 2048 + j * 512, xb + (size_t)p * C4 + j * 32);
        CP_COMMIT();
    }

    __syncthreads();   // sg/sb visible (once)

    float4 f[4];
    {
        const float4* __restrict__ E4 = (const float4*)g_Ein + (size_t)task * C4 + lane;
        #pragma unroll
        for (int j = 0; j < 4; j++) f[j] = E4[j * 32];
    }

    float2 cs = g_tab[tbase];

    for (int t = 0; t < LC; t++) {
        // keep the pipeline 3 deep; always commit to keep group counts aligned
        if (t + STAGES - 1 < LC) {
            const int tt = t + STAGES - 1;
            #pragma unroll
            for (int j = 0; j < 4; j++)
                CP16(ring_u32 + (tt & (STAGES - 1)) * 2048 + j * 512,
                     xb + (size_t)tt * C4 + j * 32);
        }
        CP_COMMIT();
        CP_WAIT3();                       // stage t ready

        // prefetch next per-t constants (register, 1 ahead)
        float2 csn = g_tab[(tbase + t + 1 < T) ? (tbase + t + 1) : (T - 1)];

        const float4* st = ring + (t & (STAGES - 1)) * 128 + lane;
        float4 cur[4];
        #pragma unroll
        for (int j = 0; j < 4; j++) cur[j] = st[j * 32];

        float4 s[4];
        float acc = 0.0f;
        #pragma unroll
        for (int j = 0; j < 4; j++) {
            f[j].x = fmaf(ALPHA, f[j].x, cur[j].x * cur[j].x);
            f[j].y = fmaf(ALPHA, f[j].y, cur[j].y * cur[j].y);
            f[j].z = fmaf(ALPHA, f[j].z, cur[j].z * cur[j].z);
            f[j].w = fmaf(ALPHA, f[j].w, cur[j].w * cur[j].w);
            float vx = fmaf(OMA, f[j].x, cs.x);
            float vy = fmaf(OMA, f[j].y, cs.x);
            float vz = fmaf(OMA, f[j].z, cs.x);
            float vw = fmaf(OMA, f[j].w, cs.x);
            s[j].x = __frsqrt_rn(vx) * vx;    // = sqrt(vx)
            s[j].y = __frsqrt_rn(vy) * vy;
            s[j].z = __frsqrt_rn(vz) * vz;
            s[j].w = __frsqrt_rn(vw) * vw;
            acc += (s[j].x + s[j].y) + (s[j].z + s[j].w);
        }
        acc += __shfl_xor_sync(0xffffffffu, acc, 16);
        acc += __shfl_xor_sync(0xffffffffu, acc, 8);
        acc += __shfl_xor_sync(0xffffffffu, acc, 4);
        acc += __shfl_xor_sync(0xffffffffu, acc, 2);
        acc += __shfl_xor_sync(0xffffffffu, acc, 1);

        // n_c = s_c / (mean + EPS*sqrt(D)); y = x*(1 + gamma*n) + beta
        const float inv = __fdividef(1.0f, fmaf(acc, 1.0f / C, cs.y));

        #pragma unroll
        for (int j = 0; j < 4; j++) {
            const float4 g4 = sg[lane + j * 32];
            const float4 b4 = sb[lane + j * 32];
            float4 o;
            o.x = fmaf(cur[j].x, fmaf(g4.x, s[j].x * inv, 1.0f), b4.x);
            o.y = fmaf(cur[j].y, fmaf(g4.y, s[j].y * inv, 1.0f), b4.y);
            o.z = fmaf(cur[j].z, fmaf(g4.z, s[j].z * inv, 1.0f), b4.z);
            o.w = fmaf(cur[j].w, fmaf(g4.w, s[j].w * inv, 1.0f), b4.w);
            yb[(size_t)t * C4 + j * 32] = o;
        }
        cs = csn;
    }
}

extern "C" void kernel_launch(void* const* d_in, const int* in_sizes, int n_in,
                              void* d_out, int out_size) {
    const float* x     = (const float*)d_in[0];
    const float* gamma = (const float*)d_in[1];
    const float* beta  = (const float*)d_in[2];
    float* y           = (float*)d_out;

    static int smem_set = 0;
    if (!smem_set) {
        cudaFuncSetAttribute(pass3_kernel,
                             cudaFuncAttributeMaxDynamicSharedMemorySize, SMEM_BYTES);
        smem_set = 1;
    }

    pass1_kernel<<<NTASK / WPB, 256>>>(x);
    pass2_kernel<<<(B * C + 255) / 256, 256>>>();
    pass3_kernel<<<NTASK / WPB, 256, SMEM_BYTES>>>(x, gamma, beta, y);
}